// round 11
// baseline (speedup 1.0000x reference)
#include <cuda_runtime.h>
#include <stdint.h>

// FullPairwise (non-PBC), output float32 concat:
//   [0    , 2MP)  atom_index12  (row0 = i + m*N, row1 = j + m*N)
//   [2MP  , 5MP)  shift_values  (zeros, [MP,3])
//   [5MP  , 6MP)  mask          (d2 <= cutoff^2 as 0/1; NaN coords -> 0)
// MP = M*P, P = N*(N-1)/2, triu(k=1) row-major pair order.
//
// g_ncoords4 holds NEGATED coords (NaN for species==-1), so x_i - x_j is
// computed as x_i + nx_j (IEEE-identical), enabling packed f32x2 arithmetic.

#define MAX_ATOMS 16384
__device__ float4 g_ncoords4[MAX_ATOMS];

typedef unsigned long long u64;

__device__ __forceinline__ u64 pk2(float lo, float hi) {
    u64 r; asm("mov.b64 %0, {%1, %2};" : "=l"(r) : "f"(lo), "f"(hi)); return r;
}
__device__ __forceinline__ void upk2(float& lo, float& hi, u64 v) {
    asm("mov.b64 {%0, %1}, %2;" : "=f"(lo), "=f"(hi) : "l"(v));
}
__device__ __forceinline__ u64 addx2(u64 a, u64 b) {
    u64 r; asm("add.rn.f32x2 %0, %1, %2;" : "=l"(r) : "l"(a), "l"(b)); return r;
}
__device__ __forceinline__ u64 mulx2(u64 a, u64 b) {
    u64 r; asm("mul.rn.f32x2 %0, %1, %2;" : "=l"(r) : "l"(a), "l"(b)); return r;
}

__global__ void pack_coords(const int* __restrict__ species,
                            const float* __restrict__ coords, int total) {
    int a = blockIdx.x * blockDim.x + threadIdx.x;
    if (a < total) {
        float x = coords[3 * a + 0];
        float y = coords[3 * a + 1];
        float z = coords[3 * a + 2];
        if (species[a] == -1) {
            x = __int_as_float(0x7fc00000);  // NaN -> mask false (matches ref)
            y = x; z = x;
        }
        g_ncoords4[a] = make_float4(-x, -y, -z, 0.0f);
    }
}

// Scalar mask: ci positive components, ncj negated. Exact rounding match.
__device__ __forceinline__ float mask_s(float cix, float ciy, float ciz,
                                        float4 ncj, float c2) {
    float dx = __fadd_rn(cix, ncj.x);
    float dy = __fadd_rn(ciy, ncj.y);
    float dz = __fadd_rn(ciz, ncj.z);
    float d2 = __fadd_rn(__fadd_rn(__fmul_rn(dx, dx), __fmul_rn(dy, dy)),
                         __fmul_rn(dz, dz));
    return (d2 <= c2) ? 1.0f : 0.0f;
}

// ---------- fast merged path (requires MP%4==0: regions phase-equal) ----------
__device__ __forceinline__ void do_row_fast(float* __restrict__ out, int m, int i,
                                            int N, long long P, long long MP,
                                            float c2, int tx, int bs) {
    long long rowstart = (long long)i * (N - 1) - ((long long)i * (i - 1)) / 2;
    int L = N - 1 - i;
    long long base = (long long)m * P + rowstart;
    const float4* __restrict__ cm4 = g_ncoords4 + (size_t)m * N;
    float4 nci = cm4[i];
    float cix = -nci.x, ciy = -nci.y, ciz = -nci.z;   // restore sign (exact)
    u64 cixx = pk2(cix, cix), ciyy = pk2(ciy, ciy), cizz = pk2(ciz, ciz);

    int moff = m * N;
    float fi  = (float)(i + moff);
    float fj0 = (float)(i + 1 + moff);

    int h = (int)((4 - (base & 3)) & 3); if (h > L) h = L;
    if (tx < h) {
        int t = tx;
        out[base + t]          = fi;
        out[MP + base + t]     = fj0 + (float)t;
        out[5 * MP + base + t] = mask_s(cix, ciy, ciz, cm4[i + 1 + t], c2);
    }
    int nv = (L - h) >> 2;
    float4* __restrict__ p0 = (float4*)(out + base + h);
    float4* __restrict__ p1 = (float4*)(out + MP + base + h);
    float4* __restrict__ p3 = (float4*)(out + 5 * MP + base + h);
    float4 v0 = make_float4(fi, fi, fi, fi);
    for (int k = tx; k < nv; k += bs) {
        int j = i + 1 + h + 4 * k;
        float4 n0 = __ldg(cm4 + j);
        float4 n1 = __ldg(cm4 + j + 1);
        float4 n2 = __ldg(cm4 + j + 2);
        float4 n3 = __ldg(cm4 + j + 3);

        u64 dx01 = addx2(cixx, pk2(n0.x, n1.x));
        u64 dy01 = addx2(ciyy, pk2(n0.y, n1.y));
        u64 dz01 = addx2(cizz, pk2(n0.z, n1.z));
        u64 dx23 = addx2(cixx, pk2(n2.x, n3.x));
        u64 dy23 = addx2(ciyy, pk2(n2.y, n3.y));
        u64 dz23 = addx2(cizz, pk2(n2.z, n3.z));

        u64 d01 = addx2(addx2(mulx2(dx01, dx01), mulx2(dy01, dy01)),
                        mulx2(dz01, dz01));
        u64 d23 = addx2(addx2(mulx2(dx23, dx23), mulx2(dy23, dy23)),
                        mulx2(dz23, dz23));

        float d0, d1, d2v, d3;
        upk2(d0, d1, d01);
        upk2(d2v, d3, d23);

        p0[k] = v0;
        float f = fj0 + (float)(h + 4 * k);
        p1[k] = make_float4(f, f + 1.0f, f + 2.0f, f + 3.0f);
        float4 r;
        r.x = (d0  <= c2) ? 1.0f : 0.0f;
        r.y = (d1  <= c2) ? 1.0f : 0.0f;
        r.z = (d2v <= c2) ? 1.0f : 0.0f;
        r.w = (d3  <= c2) ? 1.0f : 0.0f;
        p3[k] = r;
    }
    int t = h + 4 * nv + tx;
    if (t < L) {
        out[base + t]          = fi;
        out[MP + base + t]     = fj0 + (float)t;
        out[5 * MP + base + t] = mask_s(cix, ciy, ciz, cm4[i + 1 + t], c2);
    }
}

// ---------- generic fallback (arbitrary alignment) ----------
__device__ __forceinline__ void fill_const(float* __restrict__ out, long long b,
                                           int len, float v, int tx, int bs) {
    int h = (int)((4 - (b & 3)) & 3); if (h > len) h = len;
    for (int t = tx; t < h; t += bs) out[b + t] = v;
    int nv = (len - h) >> 2;
    float4* vp = (float4*)(out + b + h);
    float4 v4 = make_float4(v, v, v, v);
    for (int k = tx; k < nv; k += bs) vp[k] = v4;
    for (int t = h + 4 * nv + tx; t < len; t += bs) out[b + t] = v;
}
__device__ __forceinline__ void fill_linear(float* __restrict__ out, long long b,
                                            int len, float f0, int tx, int bs) {
    int h = (int)((4 - (b & 3)) & 3); if (h > len) h = len;
    for (int t = tx; t < h; t += bs) out[b + t] = f0 + (float)t;
    int nv = (len - h) >> 2;
    float4* vp = (float4*)(out + b + h);
    for (int k = tx; k < nv; k += bs) {
        float f = f0 + (float)(h + 4 * k);
        vp[k] = make_float4(f, f + 1.0f, f + 2.0f, f + 3.0f);
    }
    for (int t = h + 4 * nv + tx; t < len; t += bs) out[b + t] = f0 + (float)t;
}
__device__ __forceinline__ void do_row_generic(float* __restrict__ out, int m, int i,
                                               int N, long long P, long long MP,
                                               float c2, int tx, int bs) {
    long long rowstart = (long long)i * (N - 1) - ((long long)i * (i - 1)) / 2;
    int L = N - 1 - i;
    long long base = (long long)m * P + rowstart;
    const float4* __restrict__ cm4 = g_ncoords4 + (size_t)m * N;
    float4 nci = cm4[i];
    float cix = -nci.x, ciy = -nci.y, ciz = -nci.z;
    int moff = m * N;
    fill_const (out, base,          L, (float)(i + moff),     tx, bs);
    fill_linear(out, MP + base,     L, (float)(i + 1 + moff), tx, bs);
    {
        long long b = 5 * MP + base;
        for (int t = tx; t < L; t += bs)
            out[b + t] = mask_s(cix, ciy, ciz, cm4[i + 1 + t], c2);
    }
}

__global__ void __launch_bounds__(256, 6)
fullpairwise_kernel(float* __restrict__ out,
                    int N, int bpm, long long P, long long MP, float c2,
                    int fast) {
    int bid = blockIdx.x;
    int b = bid % bpm;
    int m = bid / bpm;
    int R = N - 1;
    int r1 = b;
    int r2 = R - 1 - b;
    int tx = threadIdx.x, bs = blockDim.x;

    // ---- flat zeros region: 3MP floats, contiguous aligned slice per block ----
    {
        long long Z = 3 * MP;
        long long g = gridDim.x;
        long long zc = ((Z + g - 1) / g + 3) & ~3LL;
        long long s = (long long)bid * zc;
        long long e = s + zc; if (e > Z) e = Z;
        if (s < e) {
            long long zb = 2 * MP + s;
            int len = (int)(e - s);
            int h = (int)((4 - (zb & 3)) & 3); if (h > len) h = len;
            if (tx < h) out[zb + tx] = 0.0f;
            int nv = (len - h) >> 2;
            float4* vp = (float4*)(out + zb + h);
            float4 z4 = make_float4(0.f, 0.f, 0.f, 0.f);
            #pragma unroll 4
            for (int k = tx; k < nv; k += bs) vp[k] = z4;
            int t = h + 4 * nv + tx;
            if (t < len) out[zb + t] = 0.0f;
        }
    }

    if (fast) {
        do_row_fast(out, m, r1, N, P, MP, c2, tx, bs);
        if (r2 > r1) do_row_fast(out, m, r2, N, P, MP, c2, tx, bs);
    } else {
        do_row_generic(out, m, r1, N, P, MP, c2, tx, bs);
        if (r2 > r1) do_row_generic(out, m, r2, N, P, MP, c2, tx, bs);
    }
}

extern "C" void kernel_launch(void* const* d_in, const int* in_sizes, int n_in,
                              void* d_out, int out_size) {
    const int*   species = (const int*)d_in[0];
    const float* coords  = (const float*)d_in[1];
    float* out = (float*)d_out;

    long long MN = in_sizes[0];                        // M * N
    long long Nm1 = (long long)out_size / (3 * MN);    // out_size = 3*M*N*(N-1)
    int N = (int)Nm1 + 1;
    int M = (int)(MN / N);
    long long P  = (long long)N * (N - 1) / 2;
    long long MP = (long long)M * P;

    int total = (int)MN;
    pack_coords<<<(total + 255) / 256, 256>>>(species, coords, total);

    const float c = 5.2f;
    int R = N - 1;
    int bpm = (R + 1) / 2;
    int blocks = M * bpm;
    int fast = (MP % 4 == 0) ? 1 : 0;
    fullpairwise_kernel<<<blocks, 256>>>(out, N, bpm, P, MP, c * c, fast);
}

// round 13
// speedup vs baseline: 1.0985x; 1.0985x over previous
#include <cuda_runtime.h>
#include <stdint.h>

// FullPairwise (non-PBC), output float32 concat:
//   [0    , 2MP)  atom_index12  (row0 = i + m*N, row1 = j + m*N)
//   [2MP  , 5MP)  shift_values  (zeros, [MP,3])
//   [5MP  , 6MP)  mask          (d2 <= cutoff^2 as 0/1; NaN coords -> 0)
// MP = M*P, P = N*(N-1)/2, triu(k=1) row-major pair order.
//
// Strided scalar main loop: coalesced LDG.128 coords (16B/lane), coalesced
// STG.32 outputs (1 wavefront each). Row pairing (i, N-2-i) balances blocks.
// All offsets int32 (out_size is int, so 6MP < 2^31).

#define MAX_ATOMS 16384
__device__ float4 g_coords4[MAX_ATOMS];

__global__ void pack_coords(const int* __restrict__ species,
                            const float* __restrict__ coords, int total) {
    int a = blockIdx.x * blockDim.x + threadIdx.x;
    if (a < total) {
        float x = coords[3 * a + 0];
        float y = coords[3 * a + 1];
        float z = coords[3 * a + 2];
        if (species[a] == -1) {
            x = __int_as_float(0x7fc00000);  // NaN -> mask false (matches ref)
            y = x; z = x;
        }
        g_coords4[a] = make_float4(x, y, z, 0.0f);
    }
}

__device__ __forceinline__ float mask1(float cix, float ciy, float ciz,
                                       float4 cj, float c2) {
    float dx = __fsub_rn(cix, cj.x);
    float dy = __fsub_rn(ciy, cj.y);
    float dz = __fsub_rn(ciz, cj.z);
    float d2 = __fadd_rn(__fadd_rn(__fmul_rn(dx, dx), __fmul_rn(dy, dy)),
                         __fmul_rn(dz, dz));
    return (d2 <= c2) ? 1.0f : 0.0f;
}

__device__ __forceinline__ void st_cs(float* p, float v) {
    asm volatile("st.global.cs.f32 [%0], %1;" :: "l"(p), "f"(v) : "memory");
}
__device__ __forceinline__ void st_cs4(float4* p, float4 v) {
    asm volatile("st.global.cs.v4.f32 [%0], {%1,%2,%3,%4};"
                 :: "l"(p), "f"(v.x), "f"(v.y), "f"(v.z), "f"(v.w) : "memory");
}

__device__ __forceinline__ void do_row(float* __restrict__ out, int m, int i,
                                       int N, int P, int MP, float c2,
                                       int tx, int bs) {
    int rowstart = i * (N - 1) - (i * (i - 1)) / 2;
    int L = N - 1 - i;
    int base = m * P + rowstart;
    const float4* __restrict__ cm4 = g_coords4 + m * N;
    float4 ci = cm4[i];
    float cix = ci.x, ciy = ci.y, ciz = ci.z;
    int moff = m * N;
    float fi  = (float)(i + moff);
    float fj0 = (float)(i + 1 + moff);

    float* __restrict__ o0 = out + base;
    float* __restrict__ o1 = out + MP + base;
    float* __restrict__ o2 = out + 5 * MP + base;
    const float4* __restrict__ cj = cm4 + i + 1;

    #pragma unroll 4
    for (int t = tx; t < L; t += bs) {
        float4 c = __ldg(cj + t);
        st_cs(o0 + t, fi);
        st_cs(o1 + t, fj0 + (float)t);
        st_cs(o2 + t, mask1(cix, ciy, ciz, c, c2));
    }
}

__global__ void __launch_bounds__(256)
fullpairwise_kernel(float* __restrict__ out,
                    int N, int bpm, int P, int MP, float c2) {
    int bid = blockIdx.x;
    int b = bid % bpm;
    int m = bid / bpm;
    int R = N - 1;
    int r1 = b;
    int r2 = R - 1 - b;
    int tx = threadIdx.x, bs = blockDim.x;

    // ---- flat zeros region: 3MP floats, contiguous aligned slice per block ----
    {
        int Z = 3 * MP;
        int g = gridDim.x;
        int zc = ((Z + g - 1) / g + 3) & ~3;
        int s = bid * zc;
        int e = s + zc; if (e > Z) e = Z;
        if (s < e) {
            int zb = 2 * MP + s;
            int len = e - s;
            int h = (4 - (zb & 3)) & 3; if (h > len) h = len;
            if (tx < h) out[zb + tx] = 0.0f;
            int nv = (len - h) >> 2;
            float4* vp = (float4*)(out + zb + h);
            float4 z4 = make_float4(0.f, 0.f, 0.f, 0.f);
            #pragma unroll 4
            for (int k = tx; k < nv; k += bs) st_cs4(vp + k, z4);
            int t = h + 4 * nv + tx;
            if (t < len) out[zb + t] = 0.0f;
        }
    }

    do_row(out, m, r1, N, P, MP, c2, tx, bs);
    if (r2 > r1)
        do_row(out, m, r2, N, P, MP, c2, tx, bs);
}

extern "C" void kernel_launch(void* const* d_in, const int* in_sizes, int n_in,
                              void* d_out, int out_size) {
    const int*   species = (const int*)d_in[0];
    const float* coords  = (const float*)d_in[1];
    float* out = (float*)d_out;

    long long MN = in_sizes[0];                        // M * N
    long long Nm1 = (long long)out_size / (3 * MN);    // out_size = 3*M*N*(N-1)
    int N = (int)Nm1 + 1;
    int M = (int)(MN / N);
    int P  = (int)((long long)N * (N - 1) / 2);
    int MP = M * P;

    int total = (int)MN;
    pack_coords<<<(total + 255) / 256, 256>>>(species, coords, total);

    const float c = 5.2f;
    int R = N - 1;
    int bpm = (R + 1) / 2;
    int blocks = M * bpm;
    fullpairwise_kernel<<<blocks, 256>>>(out, N, bpm, P, MP, c * c);
}